// round 13
// baseline (speedup 1.0000x reference)
#include <cuda_runtime.h>
#include <cstdint>
#include <math.h>

// Problem constants (fixed by reference setup_inputs)
#define NB 16
#define NH 1024
#define NW 1024
#define GRID_ELEMS (NB * NH * NW)   // 16777216 floats for odo_grid
#define K_OUT 64                    // 4 * B rows in odo

#define NBLOCKS 1024                // single wave (<= 148 SMs * 8 blocks)
#define NTHREADS 256
#define SLICE_FLOATS (GRID_ELEMS / NBLOCKS)   // 16384 floats = 64KB per block
#define SBUF_BYTES 16384                      // 16KB zero source in SMEM
#define NCOPIES ((SLICE_FLOATS * 4) / SBUF_BYTES)  // 4 bulk copies per block

// Single fused kernel; grid zeroing via TMA bulk stores (UTMASTG) instead of
// STG.128 (which pays a 12-cyc LSU issue cost per 512B warp-store and was the
// measured bottleneck). A 16KB zeroed SMEM buffer serves as the read-only
// source for 4 destination copies covering this block's contiguous 64KB
// slice. One instruction per 16KB vs ~32 STG.128 per warp.
//  - warp 0 computes the sparse keys (proven single-warp logic: fp32 inverse
//    affine map; true matches provably within +/-1 of the rounded center;
//    serial h-outer/w-inner 3x3 scan => pre-sorted keys; shfl prefix sum =>
//    argwhere offsets). Block 0's warp 0 writes the whole odo tail.
//  - tid 0 issues the bulk copies, waits for completion, then patches any
//    key inside its own slice (completion-ordered WAW; slices disjoint).
__global__ void __launch_bounds__(NTHREADS, 8)
odo_fused_kernel(const float* __restrict__ rot,
                 float* __restrict__ out, int out_size) {
    __shared__ __align__(128) float4 sbuf[SBUF_BYTES / 16];
    __shared__ int s_keys[K_OUT];
    __shared__ int s_nk;
    const unsigned fullmask = 0xFFFFFFFFu;
    int tid = threadIdx.x;
    int bid = blockIdx.x;
    bool tail_ok = (out_size >= GRID_ELEMS + 2 * K_OUT);

    // ---- Phase A: warp 0 computes the sparse keys ----
    if (tid < 32) {
        int lane = tid;
        int cnt = 0;
        int keys[6];

        if (lane < NB) {
            int b = lane;
            float t00 = rot[b * 6 + 0];  // ca
            float t01 = rot[b * 6 + 1];  // -sa
            float t02 = rot[b * 6 + 2];  // tx
            float t10 = rot[b * 6 + 3];  // sa
            float t11 = rot[b * 6 + 4];  // ca
            float t12 = rot[b * 6 + 5];  // ty

            // Continuous grid coords hitting (ix,iy)=(200,500):
            //   ix = 512*(grid_x+1) - 0.5  =>  grid_x* = 200.5/512 - 1
            const float gxs = 200.5f / 512.0f - 1.0f;
            const float gys = 500.5f / 512.0f - 1.0f;
            float rx = gxs - t02;
            float ry = gys - t12;
            // Rotation (det=1): inverse = transpose.
            float gx0 = t00 * rx + t10 * ry;
            float gy0 = t01 * rx + t11 * ry;
            float w0 = 512.0f * (gx0 + 1.0f) - 0.5f;
            float h0 = 512.0f * (gy0 + 1.0f) - 0.5f;

            int wr = (int)floorf(w0 + 0.5f);
            int hr = (int)floorf(h0 + 0.5f);

            // Serial 3x3 scan, h outer / w inner => keys pre-sorted.
            #pragma unroll
            for (int dh = -1; dh <= 1; dh++) {
                #pragma unroll
                for (int dw = -1; dw <= 1; dw++) {
                    int hc = hr + dh;
                    int wc = wr + dw;
                    if (wc >= 0 && wc < NW && hc >= 0 && hc < NH) {
                        // Exact float32 forward eval (reference formula).
                        float gx = (2.0f * (float)wc + 1.0f) / 1024.0f - 1.0f;
                        float gy = (2.0f * (float)hc + 1.0f) / 1024.0f - 1.0f;
                        float grid_x = t00 * gx + t01 * gy + t02;
                        float grid_y = t10 * gx + t11 * gy + t12;
                        float ixf = ((grid_x + 1.0f) * 1024.0f - 1.0f) * 0.5f;
                        float iyf = ((grid_y + 1.0f) * 1024.0f - 1.0f) * 0.5f;
                        // jnp.round = round-half-to-even = rintf (RN mode)
                        float rxf = rintf(ixf);
                        float ryf = rintf(iyf);
                        rxf = fminf(fmaxf(rxf, 0.0f), (float)(NW - 1));
                        ryf = fminf(fmaxf(ryf, 0.0f), (float)(NH - 1));
                        if (rxf == 200.0f && ryf == 500.0f && cnt < 6) {
                            keys[cnt++] = (b * NH + hc) * NW + wc;
                        }
                    }
                }
            }
        }

        // Warp-inclusive prefix sum over per-lane counts.
        int inc = cnt;
        #pragma unroll
        for (int d = 1; d < 32; d <<= 1) {
            int v = __shfl_up_sync(fullmask, inc, d);
            if (lane >= d) inc += v;
        }
        int off = inc - cnt;                        // exclusive prefix
        int total = __shfl_sync(fullmask, inc, 31); // grand total
        if (total > K_OUT) total = K_OUT;
        if (lane == 0) s_nk = total;

        // Publish ordered keys (key = b*HW+h*W+w monotone in b => batch
        // order + per-batch sorted = global argwhere order).
        for (int i = 0; i < cnt; i++) {
            int pos = off + i;
            if (pos < K_OUT) s_keys[pos] = keys[i];
        }

        // Block 0: write the entire odo tail (pairs + -1 fill). The bulk
        // copies below never touch the tail region, so no race.
        if (bid == 0 && tail_ok) {
            float* odo = out + GRID_ELEMS;
            for (int i = 0; i < cnt; i++) {
                int pos = off + i;
                if (pos < K_OUT) {
                    int key = keys[i];
                    odo[2 * pos + 0] = (float)((key >> 10) & (NH - 1));
                    odo[2 * pos + 1] = (float)(key & (NW - 1));
                }
            }
            int tail_floats = out_size - GRID_ELEMS;
            for (int i = 2 * total + lane; i < tail_floats; i += 32) {
                odo[i] = -1.0f;
            }
        }
    }

    // ---- Phase B: zero the 16KB SMEM source buffer ----
    {
        const float4 z = make_float4(0.f, 0.f, 0.f, 0.f);
        #pragma unroll
        for (int i = tid; i < SBUF_BYTES / 16; i += NTHREADS) {
            sbuf[i] = z;
        }
    }
    __syncthreads();  // s_keys/s_nk + sbuf zeros visible block-wide

    // ---- Phase C: tid 0 issues bulk stores, waits, patches ----
    if (tid == 0) {
        // Order the generic STS zeros before the async-proxy bulk reads.
        asm volatile("fence.proxy.async;" ::: "memory");

        uint32_t saddr;
        asm("{ .reg .u64 t; cvta.to.shared.u64 t, %1; cvt.u32.u64 %0, t; }"
            : "=r"(saddr) : "l"((const void*)sbuf));

        float* slice = out + (size_t)bid * SLICE_FLOATS;
        #pragma unroll
        for (int c = 0; c < NCOPIES; c++) {
            void* gdst = (void*)((char*)slice + (size_t)c * SBUF_BYTES);
            asm volatile(
                "cp.async.bulk.global.shared::cta.bulk_group [%0], [%1], %2;"
                :: "l"(gdst), "r"(saddr), "r"((uint32_t)SBUF_BYTES)
                : "memory");
        }
        asm volatile("cp.async.bulk.commit_group;" ::: "memory");
        asm volatile("cp.async.bulk.wait_group 0;" ::: "memory");
        // Bulk stores complete; order them before the generic patch stores.
        asm volatile("fence.proxy.async;" ::: "memory");

        // Patch keys inside THIS block's slice (slices disjoint).
        int nk = s_nk;
        for (int i = 0; i < nk; i++) {
            int key = s_keys[i];
            if ((key >> 14) == bid) {  // key / SLICE_FLOATS
                out[key] = 30.0f;
            }
        }
    }
}

extern "C" void kernel_launch(void* const* d_in, const int* in_sizes, int n_in,
                              void* d_out, int out_size) {
    // Inputs per metadata order: d_in[0]=cost_map_batch (unused by the math),
    // d_in[1]=rot_mat (16x2x3 float32).
    const float* rot = (const float*)d_in[1];
    float* out = (float*)d_out;
    odo_fused_kernel<<<NBLOCKS, NTHREADS, 0, 0>>>(rot, out, out_size);
}

// round 15
// speedup vs baseline: 1.1325x; 1.1325x over previous
#include <cuda_runtime.h>
#include <cstdint>
#include <math.h>

// Problem constants (fixed by reference setup_inputs)
#define NB 16
#define NH 1024
#define NW 1024
#define GRID_ELEMS (NB * NH * NW)   // 16777216 floats for odo_grid
#define K_OUT 64                    // 4 * B rows in odo

#define NBLOCKS (148 * 8)           // 1184 = exactly ONE wave at 8 blocks/SM
#define NTHREADS 256
#define TOT (NBLOCKS * NTHREADS)    // 303104 threads

// Single fused kernel, single wave, stores-first:
//  - ALL warps begin the float4 zero loop immediately (no prologue);
//  - warp 0, after finishing its store share, computes the sparse keys
//    (proven single-warp logic: fp32 inverse affine map — true matches are
//    provably within +/-1 of the rounded center since any lattice point
//    mapping into the target unit square lies within 0.708px of the
//    continuous preimage; serial h-outer/w-inner 3x3 scan => PRE-SORTED
//    keys; shfl prefix sum => argwhere offsets). Block 0's warp 0 also
//    writes the whole odo tail (tail excluded from the zero range).
//  - one __syncthreads, then warp 0 re-stores 30.0f for keys whose zeroing
//    thread lives in THIS block (same-block same-address stores separated
//    by a barrier are coherently ordered). <=2 iterations per lane.
__global__ void __launch_bounds__(NTHREADS, 8)
odo_fused_kernel(const float* __restrict__ rot,
                 float* __restrict__ out, int out_size) {
    __shared__ int s_keys[K_OUT];
    __shared__ int s_nk;
    const unsigned fullmask = 0xFFFFFFFFu;
    int tid = threadIdx.x;
    int bid = blockIdx.x;
    int gtid = bid * NTHREADS + tid;
    bool tail_ok = (out_size >= GRID_ELEMS + 2 * K_OUT);

    // ---- Phase 1: zero the grid region (float4 grid-stride, stores-first) --
    {
        float4* out4 = (float4*)out;
        const float4 z = make_float4(0.f, 0.f, 0.f, 0.f);
        const int n4 = GRID_ELEMS >> 2;
        for (int i = gtid; i < n4; i += TOT) {
            out4[i] = z;
        }
    }

    // ---- Phase 2: warp 0 computes the sparse keys (overlaps store drain) --
    if (tid < 32) {
        int lane = tid;
        int cnt = 0;
        int keys[6];

        if (lane < NB) {
            int b = lane;
            float t00 = rot[b * 6 + 0];  // ca
            float t01 = rot[b * 6 + 1];  // -sa
            float t02 = rot[b * 6 + 2];  // tx
            float t10 = rot[b * 6 + 3];  // sa
            float t11 = rot[b * 6 + 4];  // ca
            float t12 = rot[b * 6 + 5];  // ty

            // Continuous grid coords hitting (ix,iy)=(200,500):
            //   ix = 512*(grid_x+1) - 0.5  =>  grid_x* = 200.5/512 - 1
            const float gxs = 200.5f / 512.0f - 1.0f;
            const float gys = 500.5f / 512.0f - 1.0f;
            float rx = gxs - t02;
            float ry = gys - t12;
            // Rotation (det=1): inverse = transpose.
            float gx0 = t00 * rx + t10 * ry;
            float gy0 = t01 * rx + t11 * ry;
            float w0 = 512.0f * (gx0 + 1.0f) - 0.5f;
            float h0 = 512.0f * (gy0 + 1.0f) - 0.5f;

            int wr = (int)floorf(w0 + 0.5f);
            int hr = (int)floorf(h0 + 0.5f);

            // Serial 3x3 scan, h outer / w inner => keys pre-sorted.
            #pragma unroll
            for (int dh = -1; dh <= 1; dh++) {
                #pragma unroll
                for (int dw = -1; dw <= 1; dw++) {
                    int hc = hr + dh;
                    int wc = wr + dw;
                    if (wc >= 0 && wc < NW && hc >= 0 && hc < NH) {
                        // Exact float32 forward eval (reference formula).
                        float gx = (2.0f * (float)wc + 1.0f) / 1024.0f - 1.0f;
                        float gy = (2.0f * (float)hc + 1.0f) / 1024.0f - 1.0f;
                        float grid_x = t00 * gx + t01 * gy + t02;
                        float grid_y = t10 * gx + t11 * gy + t12;
                        float ixf = ((grid_x + 1.0f) * 1024.0f - 1.0f) * 0.5f;
                        float iyf = ((grid_y + 1.0f) * 1024.0f - 1.0f) * 0.5f;
                        // jnp.round = round-half-to-even = rintf (RN mode)
                        float rxf = rintf(ixf);
                        float ryf = rintf(iyf);
                        rxf = fminf(fmaxf(rxf, 0.0f), (float)(NW - 1));
                        ryf = fminf(fmaxf(ryf, 0.0f), (float)(NH - 1));
                        if (rxf == 200.0f && ryf == 500.0f && cnt < 6) {
                            keys[cnt++] = (b * NH + hc) * NW + wc;
                        }
                    }
                }
            }
        }

        // Warp-inclusive prefix sum over per-lane counts.
        int inc = cnt;
        #pragma unroll
        for (int d = 1; d < 32; d <<= 1) {
            int v = __shfl_up_sync(fullmask, inc, d);
            if (lane >= d) inc += v;
        }
        int off = inc - cnt;                        // exclusive prefix
        int total = __shfl_sync(fullmask, inc, 31); // grand total
        if (total > K_OUT) total = K_OUT;
        if (lane == 0) s_nk = total;

        // Publish ordered keys (key = b*HW+h*W+w monotone in b => batch
        // order + per-batch sorted = global argwhere order).
        for (int i = 0; i < cnt; i++) {
            int pos = off + i;
            if (pos < K_OUT) s_keys[pos] = keys[i];
        }

        // Block 0: write the entire odo tail (pairs + -1 fill). The zero
        // loop never touches the tail region, so no race.
        if (bid == 0 && tail_ok) {
            float* odo = out + GRID_ELEMS;
            for (int i = 0; i < cnt; i++) {
                int pos = off + i;
                if (pos < K_OUT) {
                    int key = keys[i];
                    odo[2 * pos + 0] = (float)((key >> 10) & (NH - 1));
                    odo[2 * pos + 1] = (float)(key & (NW - 1));
                }
            }
            int tail_floats = out_size - GRID_ELEMS;
            for (int i = 2 * total + lane; i < tail_floats; i += 32) {
                odo[i] = -1.0f;
            }
        }
    }

    // Block-scope barrier: orders this block's zero-stores before the patch
    // stores below (same block, same address => coherent), and makes
    // s_keys/s_nk visible to warp 0's patch pass.
    __syncthreads();

    // ---- Phase 3: warp 0 patches keys owned by THIS block ----
    if (tid < 32) {
        int nk = s_nk;
        #pragma unroll
        for (int r = 0; r < 2; r++) {
            int idx = tid + 32 * r;
            if (idx < nk) {
                int key = s_keys[idx];
                int owner_thread = (key >> 2) % TOT;  // thread that zeroed it
                if ((owner_thread >> 8) == bid) {     // /NTHREADS
                    out[key] = 30.0f;
                }
            }
        }
    }
}

extern "C" void kernel_launch(void* const* d_in, const int* in_sizes, int n_in,
                              void* d_out, int out_size) {
    // Inputs per metadata order: d_in[0]=cost_map_batch (unused by the math),
    // d_in[1]=rot_mat (16x2x3 float32).
    const float* rot = (const float*)d_in[1];
    float* out = (float*)d_out;
    odo_fused_kernel<<<NBLOCKS, NTHREADS, 0, 0>>>(rot, out, out_size);
}